// round 3
// baseline (speedup 1.0000x reference)
#include <cuda_runtime.h>
#include <cooperative_groups.h>
namespace cg = cooperative_groups;

#define BATCH 256
#define SEQ 512
#define HID 128
#define GATES 512
#define WSTR 132
#define WSL (128*WSTR)

__device__ float g_P2[100*GATES];
__device__ __align__(8) unsigned char g_maskT[SEQ*BATCH];
__device__ unsigned char g_idxT[SEQ*BATCH];
__device__ float g_sent[(size_t)BATCH*SEQ*HID];
__device__ float g_beta[BATCH*HID];
__device__ float g_gamma[BATCH*HID];

__device__ __forceinline__ float sigm(float x){ return 1.f/(1.f+expf(-x)); }

// z[g] += sum_k h[k] * W[(g*32)*WSTR + k]   (W pre-offset by owned col i)
__device__ __forceinline__ void acc4(const float* __restrict__ W, const float* __restrict__ h, float z[4]){
#pragma unroll 8
    for(int k=0;k<HID;k+=4){
        float4 hv = *(const float4*)(h+k);
#pragma unroll
        for(int g=0;g<4;g++){
            float4 w = *(const float4*)(W + g*32*WSTR + k);
            z[g]=fmaf(hv.x,w.x,z[g]); z[g]=fmaf(hv.y,w.y,z[g]);
            z[g]=fmaf(hv.z,w.z,z[g]); z[g]=fmaf(hv.w,w.w,z[g]);
        }
    }
}

__global__ void k_trans(const int* __restrict__ ch, const int* __restrict__ wd){
    int t=blockIdx.x, b=threadIdx.x;
    int c=ch[b*SEQ+t], w=wd[b*SEQ+t];
    g_maskT[t*BATCH+b]=(unsigned char)(c==0);
    g_idxT [t*BATCH+b]=(unsigned char)(c*10+w);
}

__global__ void k_table(const float* __restrict__ emb_char,const float* __restrict__ emb_word,
                        const float* __restrict__ Wwc,const float* __restrict__ bwc,
                        const float* __restrict__ l1_Wx,const float* __restrict__ l1_b){
    __shared__ float xv[64];
    int tid=threadIdx.x; // 512
    for(int p=0;p<100;p++){
        int c=p/10, w=p%10;
        if(tid<64){
            float s=emb_char[c*64+tid]+bwc[tid];
            for(int d=0;d<32;d++) s=fmaf(emb_word[w*32+d],Wwc[d*64+tid],s);
            xv[tid]=s;
        }
        __syncthreads();
        float acc=l1_b[tid];
        for(int e=0;e<64;e++) acc=fmaf(xv[e],l1_Wx[e*GATES+tid],acc);
        g_P2[p*GATES+tid]=acc;
        __syncthreads();
    }
}

__global__ void __cluster_dims__(4,1,1) __launch_bounds__(256,1)
k_lstm(const float* __restrict__ Wh1g,const float* __restrict__ Wx2g,
       const float* __restrict__ Wh2g,const float* __restrict__ b2g){
    extern __shared__ float sm[];
    float* W1 = sm;
    float* W2x= sm+WSL;
    float* W2h= sm+2*WSL;
    float* h1b= sm+3*WSL;      // [2][8][128] = 2048 floats
    float* h2b= h1b+2048;      // [2][8][128] = 2048 floats
    float* b2s= h2b+2048;      // [128]
    const int tid=threadIdx.x, o=blockIdx.x&3, cl=blockIdx.x>>2;
    const int i=tid&31, r=tid>>5, b=cl*8+r;

    for(int idx=tid; idx<128*128; idx+=256){
        int j=idx&127, k=idx>>7;
        int gc=(j>>5)*128 + o*32 + (j&31);
        W1 [j*WSTR+k]=Wh1g[k*GATES+gc];
        W2x[j*WSTR+k]=Wx2g[k*GATES+gc];
        W2h[j*WSTR+k]=Wh2g[k*GATES+gc];
    }
    if(tid<128) b2s[tid]=b2g[(tid>>5)*128+o*32+(tid&31)];
    // FIX (was idx<4096 -> OOB smem write): each buffer is exactly 2048 floats.
    for(int idx=tid; idx<2048; idx+=256){ h1b[idx]=0.f; h2b[idx]=0.f; }

    cg::cluster_group cluster=cg::this_cluster();
    float* ph1[4]; float* ph2[4];
#pragma unroll
    for(int rk=0;rk<4;rk++){ ph1[rk]=cluster.map_shared_rank(h1b,rk); ph2[rk]=cluster.map_shared_rank(h2b,rk); }
    cluster.sync();

    float c1=0.f, c2=0.f; int p=0;
    const float* W1i = W1 + i*WSTR;
    const float* W2xi= W2x+ i*WSTR;
    const float* W2hi= W2h+ i*WSTR;

    for(int t=0;t<SEQ;t++){
        unsigned long long m8 = *(const unsigned long long*)(g_maskT + t*BATCH + cl*8);
        if(m8==0ull){
            g_sent[((size_t)b*SEQ+t)*HID + o*32+i] = h2b[p*1024 + r*HID + o*32+i];
            continue;
        }
        const bool act = (m8>>(8*r))&1ull;
        const int pq = p^1;
        // -------- layer 1 --------
        if(act){
            float z[4];
            const float* P = g_P2 + (int)g_idxT[t*BATCH+b]*GATES + o*32+i;
            z[0]=P[0]; z[1]=P[128]; z[2]=P[256]; z[3]=P[384];
            acc4(W1i, h1b+p*1024+r*HID, z);
            float cn = sigm(z[1])*c1 + sigm(z[0])*tanhf(z[2]); c1=cn;
            float h1n = sigm(z[3])*tanhf(cn);
#pragma unroll
            for(int rk=0;rk<4;rk++) ph1[rk][pq*1024 + r*HID + o*32+i] = h1n;
        }
        for(int idx=tid; idx<1024; idx+=256)
            if(!((m8>>(8*(idx>>7)))&1ull)) h1b[pq*1024+idx]=h1b[p*1024+idx];
        cluster.sync();
        // -------- layer 2 --------
        float h2v;
        if(act){
            float z[4];
            z[0]=b2s[i]; z[1]=b2s[32+i]; z[2]=b2s[64+i]; z[3]=b2s[96+i];
            acc4(W2xi, h1b+pq*1024+r*HID, z);
            acc4(W2hi, h2b+p*1024+r*HID, z);
            float cn = sigm(z[1])*c2 + sigm(z[0])*tanhf(z[2]); c2=cn;
            h2v = sigm(z[3])*tanhf(cn);
#pragma unroll
            for(int rk=0;rk<4;rk++) ph2[rk][pq*1024 + r*HID + o*32+i] = h2v;
        }else{
            h2v = h2b[p*1024 + r*HID + o*32+i];
        }
        for(int idx=tid; idx<1024; idx+=256)
            if(!((m8>>(8*(idx>>7)))&1ull)) h2b[pq*1024+idx]=h2b[p*1024+idx];
        g_sent[((size_t)b*SEQ+t)*HID + o*32+i] = h2v;
        cluster.sync();
        p=pq;
    }
}

__global__ void k_subject(const int* __restrict__ subj,
                          const float* __restrict__ betaW,const float* __restrict__ betab,
                          const float* __restrict__ gammaW,const float* __restrict__ gammab){
    __shared__ float sub[256];
    int b=blockIdx.x, tid=threadIdx.x; // 128 threads
    int s0=subj[b*2+0], s1=subj[b*2+1];
    sub[tid]     = g_sent[((size_t)b*SEQ+s0)*HID+tid];
    sub[128+tid] = g_sent[((size_t)b*SEQ+s1)*HID+tid];
    __syncthreads();
    float ab=betab[tid], ag=gammab[tid];
    for(int k=0;k<256;k++){
        float v=sub[k];
        ab=fmaf(v,betaW [k*HID+tid],ab);
        ag=fmaf(v,gammaW[k*HID+tid],ag);
    }
    g_beta [b*HID+tid]=ab;
    g_gamma[b*HID+tid]=ag;
}

__global__ void __launch_bounds__(256) k_post(const float* __restrict__ poW,const float* __restrict__ pob,
                                              const float* __restrict__ subW,const float* __restrict__ subb,
                                              float* __restrict__ out){
    __shared__ float rowS[8][132];
    __shared__ float ctxS[8][132];
    int warp=threadIdx.x>>5, lane=threadIdx.x&31;
    size_t rid=(size_t)blockIdx.x*8+warp;      // b*512+t
    int b=(int)(rid>>9);
    const float* row=g_sent+rid*HID;
    float x0=row[lane], x1=row[lane+32], x2=row[lane+64], x3=row[lane+96];
    float s=x0+x1+x2+x3, q=x0*x0+x1*x1+x2*x2+x3*x3;
#pragma unroll
    for(int d=16;d;d>>=1){ s+=__shfl_xor_sync(0xffffffffu,s,d); q+=__shfl_xor_sync(0xffffffffu,q,d); }
    float u=s*(1.f/128.f);
    float v=fmaxf(q*(1.f/128.f)-u*u,0.f);
    float inv=rsqrtf(v+1e-12f);
    const float* gma=g_gamma+b*HID; const float* bta=g_beta+b*HID;
    rowS[warp][lane]   =x0; ctxS[warp][lane]   =fmaf(gma[lane]   *inv,(x0-u),bta[lane]);
    rowS[warp][lane+32]=x1; ctxS[warp][lane+32]=fmaf(gma[lane+32]*inv,(x1-u),bta[lane+32]);
    rowS[warp][lane+64]=x2; ctxS[warp][lane+64]=fmaf(gma[lane+64]*inv,(x2-u),bta[lane+64]);
    rowS[warp][lane+96]=x3; ctxS[warp][lane+96]=fmaf(gma[lane+96]*inv,(x3-u),bta[lane+96]);
    __syncwarp();
    if(lane<20){
        float acc=pob[lane];
#pragma unroll 4
        for(int k=0;k<HID;k++) acc=fmaf(ctxS[warp][k],poW[k*20+lane],acc);
        out[(size_t)BATCH*SEQ*2 + rid*20 + lane]=acc;
    }else if(lane<22){
        int c=lane-20;
        float acc=subb[c];
#pragma unroll 4
        for(int k=0;k<HID;k++) acc=fmaf(rowS[warp][k],subW[k*2+c],acc);
        out[rid*2+c]=acc;
    }
}

extern "C" void kernel_launch(void* const* d_in, const int* in_sizes, int n_in,
                              void* d_out, int out_size){
    const int*   char_ids=(const int*)d_in[0];
    const int*   word_ids=(const int*)d_in[1];
    const int*   subj    =(const int*)d_in[2];
    const float* emb_char=(const float*)d_in[3];
    const float* emb_word=(const float*)d_in[4];
    const float* Wwc     =(const float*)d_in[5];
    const float* bwc     =(const float*)d_in[6];
    const float* l1_Wx   =(const float*)d_in[7];
    const float* l1_Wh   =(const float*)d_in[8];
    const float* l1_b    =(const float*)d_in[9];
    const float* l2_Wx   =(const float*)d_in[10];
    const float* l2_Wh   =(const float*)d_in[11];
    const float* l2_b    =(const float*)d_in[12];
    const float* beta_W  =(const float*)d_in[13];
    const float* beta_b  =(const float*)d_in[14];
    const float* gamma_W =(const float*)d_in[15];
    const float* gamma_b =(const float*)d_in[16];
    const float* sub_W   =(const float*)d_in[17];
    const float* sub_b   =(const float*)d_in[18];
    const float* po_W    =(const float*)d_in[19];
    const float* po_b    =(const float*)d_in[20];
    float* out=(float*)d_out;

    static_assert(3*WSL+2048+2048+128 == 54912, "smem layout");
    const int smem_bytes = 54912*4; // 219648
    cudaFuncSetAttribute(k_lstm, cudaFuncAttributeMaxDynamicSharedMemorySize, smem_bytes);

    k_trans<<<SEQ,BATCH>>>(char_ids,word_ids);
    k_table<<<1,512>>>(emb_char,emb_word,Wwc,bwc,l1_Wx,l1_b);
    k_lstm<<<128,256,smem_bytes>>>(l1_Wh,l2_Wx,l2_Wh,l2_b);
    k_subject<<<BATCH,HID>>>(subj,beta_W,beta_b,gamma_W,gamma_b);
    k_post<<<(BATCH*SEQ)/8,256>>>(po_W,po_b,sub_W,sub_b,out);
}

// round 4
// speedup vs baseline: 1.4087x; 1.4087x over previous
#include <cuda_runtime.h>
#include <cooperative_groups.h>
namespace cg = cooperative_groups;

#define BATCH 256
#define SEQ 512
#define HID 128
#define GATES 512
#define WSTR 132

// SMEM float offsets
#define OFF_W1   0
#define OFF_W2X  16896
#define OFF_W2H  33792
#define OFF_H1B  50688   // [2][8][128]
#define OFF_H2B  52736   // [2][8][128]
#define OFF_ZSA  54784   // [8][128]
#define OFF_ZSB  55808   // [8][128]
#define OFF_B2S  56832   // [128]
#define OFF_CM   56960   // 512 bytes
#define SMEM_FLOATS 57088

__device__ float g_P2[100*GATES];
__device__ __align__(8) unsigned char g_maskT[SEQ*BATCH];
__device__ __align__(8) unsigned char g_idxT[SEQ*BATCH];
__device__ float g_sent[(size_t)BATCH*SEQ*HID];
__device__ float g_beta[BATCH*HID];
__device__ float g_gamma[BATCH*HID];

__device__ __forceinline__ float sigm(float x){ return 0.5f*tanhf(0.5f*x)+0.5f; }

__global__ void k_trans(const int* __restrict__ ch, const int* __restrict__ wd){
    int t=blockIdx.x, b=threadIdx.x;
    int c=ch[b*SEQ+t], w=wd[b*SEQ+t];
    g_maskT[t*BATCH+b]=(unsigned char)(c==0);
    g_idxT [t*BATCH+b]=(unsigned char)(c*10+w);
}

__global__ void k_table(const float* __restrict__ emb_char,const float* __restrict__ emb_word,
                        const float* __restrict__ Wwc,const float* __restrict__ bwc,
                        const float* __restrict__ l1_Wx,const float* __restrict__ l1_b){
    __shared__ float xv[64];
    int tid=threadIdx.x; // 512
    for(int p=0;p<100;p++){
        int c=p/10, w=p%10;
        if(tid<64){
            float s=emb_char[c*64+tid]+bwc[tid];
            for(int d=0;d<32;d++) s=fmaf(emb_word[w*32+d],Wwc[d*64+tid],s);
            xv[tid]=s;
        }
        __syncthreads();
        float acc=l1_b[tid];
        for(int e=0;e<64;e++) acc=fmaf(xv[e],l1_Wx[e*GATES+tid],acc);
        g_P2[p*GATES+tid]=acc;
        __syncthreads();
    }
}

__global__ void __cluster_dims__(4,1,1) __launch_bounds__(256,1)
k_lstm(const float* __restrict__ Wh1g,const float* __restrict__ Wx2g,
       const float* __restrict__ Wh2g,const float* __restrict__ b2g){
    extern __shared__ float sm[];
    float* W1  = sm + OFF_W1;
    float* W2x = sm + OFF_W2X;
    float* W2h = sm + OFF_W2H;
    float* h1b = sm + OFF_H1B;
    float* h2b = sm + OFF_H2B;
    float* zsA = sm + OFF_ZSA;
    float* zsB = sm + OFF_ZSB;
    float* b2s = sm + OFF_B2S;
    unsigned char* cmask = (unsigned char*)(sm + OFF_CM);

    const int tid = threadIdx.x, o = blockIdx.x & 3, cl = blockIdx.x >> 2;
    // phase-1/3 role
    const int j = tid & 127, half = tid >> 7;   // term == half in phase 3
    const int gcol = (j >> 5) * 128 + o * 32 + (j & 31);
    // gate role
    const int rr = tid >> 5, ii = tid & 31;
    const int oc = o * 32 + ii;
    const int bb = cl * 8 + rr;

    // ---- prologue: weights into SMEM (coalesced over j) ----
    for (int idx = tid; idx < 128 * 128; idx += 256) {
        int jj = idx & 127, k = idx >> 7;
        int gc = (jj >> 5) * 128 + o * 32 + (jj & 31);
        W1 [jj * WSTR + k] = Wh1g[k * GATES + gc];
        W2x[jj * WSTR + k] = Wx2g[k * GATES + gc];
        W2h[jj * WSTR + k] = Wh2g[k * GATES + gc];
    }
    if (tid < 128) b2s[tid] = b2g[(tid >> 5) * 128 + o * 32 + (tid & 31)];
    for (int idx = tid; idx < 2048; idx += 256) { h1b[idx] = 0.f; h2b[idx] = 0.f; }
    for (int s = tid; s < SEQ; s += 256) {
        unsigned long long v = *(const unsigned long long*)(g_maskT + s * BATCH + cl * 8);
        unsigned mm = 0;
#pragma unroll
        for (int r = 0; r < 8; r++) mm |= ((unsigned)((v >> (8 * r)) & 1ull)) << r;
        cmask[s] = (unsigned char)mm;
    }
    __syncthreads();
    const float b2r = half ? b2s[j] : 0.f;

    cg::cluster_group cluster = cg::this_cluster();
    float* ph1[4]; float* ph2[4];
#pragma unroll
    for (int rk = 0; rk < 4; rk++) { ph1[rk] = cluster.map_shared_rank(h1b, rk); ph2[rk] = cluster.map_shared_rank(h2b, rk); }
    cluster.sync();

    const float* Wp1 = W1 + j * WSTR + half * 64;
    const float* Wt  = (half ? W2h : W2x) + j * WSTR;

    float c1 = 0.f, c2 = 0.f;
    int p = 0;

    for (int t = 0; t < SEQ; t++) {
        const int m = cmask[t];
        if (m == 0) {
            g_sent[((size_t)bb * SEQ + t) * HID + oc] = h2b[p * 1024 + rr * 128 + oc];
            continue;
        }
        const unsigned long long idx8 = *(const unsigned long long*)(g_idxT + t * BATCH + cl * 8);
        const int pq = p ^ 1;
        float* zhalf = half ? zsB : zsA;

        // ---- phase 1: L1 z, split-k over halves ----
#pragma unroll
        for (int r = 0; r < 8; r++) {
            if (!((m >> r) & 1)) continue;
            const float* hv = h1b + p * 1024 + r * 128 + half * 64;
            float pv = 0.f;
            if (half == 0) pv = g_P2[(int)((idx8 >> (8 * r)) & 255ull) * GATES + gcol];
            float z = 0.f;
#pragma unroll
            for (int k = 0; k < 64; k += 4) {
                float4 h4 = *(const float4*)(hv + k);
                float4 w4 = *(const float4*)(Wp1 + k);
                z = fmaf(h4.x, w4.x, z); z = fmaf(h4.y, w4.y, z);
                z = fmaf(h4.z, w4.z, z); z = fmaf(h4.w, w4.w, z);
            }
            zhalf[r * 128 + j] = z + pv;
        }
        __syncthreads();

        // ---- phase 2: L1 gates + h1 exchange; inactive rows forward own cols ----
        const bool act = (m >> rr) & 1;
        float h1v;
        if (act) {
            float zi = zsA[rr * 128 + ii]      + zsB[rr * 128 + ii];
            float zf = zsA[rr * 128 + 32 + ii] + zsB[rr * 128 + 32 + ii];
            float zg = zsA[rr * 128 + 64 + ii] + zsB[rr * 128 + 64 + ii];
            float zo = zsA[rr * 128 + 96 + ii] + zsB[rr * 128 + 96 + ii];
            float cn = sigm(zf) * c1 + sigm(zi) * tanhf(zg); c1 = cn;
            h1v = sigm(zo) * tanhf(cn);
        } else {
            h1v = h1b[p * 1024 + rr * 128 + oc];
            float h2k = h2b[p * 1024 + rr * 128 + oc];
#pragma unroll
            for (int rk = 0; rk < 4; rk++) ph2[rk][pq * 1024 + rr * 128 + oc] = h2k;
        }
#pragma unroll
        for (int rk = 0; rk < 4; rk++) ph1[rk][pq * 1024 + rr * 128 + oc] = h1v;

        cluster.sync();

        // ---- phase 3: L2 z, split by term (0: x-term w/ new h1, 1: h-term w/ old h2) ----
#pragma unroll
        for (int r = 0; r < 8; r++) {
            if (!((m >> r) & 1)) continue;
            const float* hv = half ? (h2b + p * 1024 + r * 128) : (h1b + pq * 1024 + r * 128);
            float z = b2r;
#pragma unroll
            for (int k = 0; k < 128; k += 4) {
                float4 h4 = *(const float4*)(hv + k);
                float4 w4 = *(const float4*)(Wt + k);
                z = fmaf(h4.x, w4.x, z); z = fmaf(h4.y, w4.y, z);
                z = fmaf(h4.z, w4.z, z); z = fmaf(h4.w, w4.w, z);
            }
            zhalf[r * 128 + j] = z;
        }
        __syncthreads();

        // ---- phase 4: L2 gates + h2 exchange + sent ----
        if (act) {
            float zi = zsA[rr * 128 + ii]      + zsB[rr * 128 + ii];
            float zf = zsA[rr * 128 + 32 + ii] + zsB[rr * 128 + 32 + ii];
            float zg = zsA[rr * 128 + 64 + ii] + zsB[rr * 128 + 64 + ii];
            float zo = zsA[rr * 128 + 96 + ii] + zsB[rr * 128 + 96 + ii];
            float cn = sigm(zf) * c2 + sigm(zi) * tanhf(zg); c2 = cn;
            float h2v = sigm(zo) * tanhf(cn);
#pragma unroll
            for (int rk = 0; rk < 4; rk++) ph2[rk][pq * 1024 + rr * 128 + oc] = h2v;
            g_sent[((size_t)bb * SEQ + t) * HID + oc] = h2v;
        } else {
            g_sent[((size_t)bb * SEQ + t) * HID + oc] = h2b[p * 1024 + rr * 128 + oc];
        }
        __syncthreads();   // protect zs buffers for next step's phase 1
        p = pq;
    }
    cluster.sync();        // no CTA exits while peers may still write its SMEM
}

__global__ void k_subject(const int* __restrict__ subj,
                          const float* __restrict__ betaW,const float* __restrict__ betab,
                          const float* __restrict__ gammaW,const float* __restrict__ gammab){
    __shared__ float sub[256];
    int b = blockIdx.x, tid = threadIdx.x;  // 256 threads
    int s0 = subj[b*2+0], s1 = subj[b*2+1];
    if (tid < 128) sub[tid]       = g_sent[((size_t)b*SEQ+s0)*HID + tid];
    else           sub[tid]       = g_sent[((size_t)b*SEQ+s1)*HID + (tid-128)];
    __syncthreads();
    int col = tid & 127;
    const float* Wm = (tid < 128) ? betaW : gammaW;
    float a = (tid < 128) ? betab[col] : gammab[col];
    for (int k = 0; k < 256; k++) a = fmaf(sub[k], Wm[k*HID + col], a);
    if (tid < 128) g_beta [b*HID + col] = a;
    else           g_gamma[b*HID + col] = a;
}

__global__ void __launch_bounds__(256) k_post(const float* __restrict__ poW,const float* __restrict__ pob,
                                              const float* __restrict__ subW,const float* __restrict__ subb,
                                              float* __restrict__ out){
    __shared__ float rowS[8][132];
    __shared__ float ctxS[8][132];
    int warp=threadIdx.x>>5, lane=threadIdx.x&31;
    size_t rid=(size_t)blockIdx.x*8+warp;      // b*512+t
    int b=(int)(rid>>9);
    const float* row=g_sent+rid*HID;
    float x0=row[lane], x1=row[lane+32], x2=row[lane+64], x3=row[lane+96];
    float s=x0+x1+x2+x3, q=x0*x0+x1*x1+x2*x2+x3*x3;
#pragma unroll
    for(int d=16;d;d>>=1){ s+=__shfl_xor_sync(0xffffffffu,s,d); q+=__shfl_xor_sync(0xffffffffu,q,d); }
    float u=s*(1.f/128.f);
    float v=fmaxf(q*(1.f/128.f)-u*u,0.f);
    float inv=rsqrtf(v+1e-12f);
    const float* gma=g_gamma+b*HID; const float* bta=g_beta+b*HID;
    rowS[warp][lane]   =x0; ctxS[warp][lane]   =fmaf(gma[lane]   *inv,(x0-u),bta[lane]);
    rowS[warp][lane+32]=x1; ctxS[warp][lane+32]=fmaf(gma[lane+32]*inv,(x1-u),bta[lane+32]);
    rowS[warp][lane+64]=x2; ctxS[warp][lane+64]=fmaf(gma[lane+64]*inv,(x2-u),bta[lane+64]);
    rowS[warp][lane+96]=x3; ctxS[warp][lane+96]=fmaf(gma[lane+96]*inv,(x3-u),bta[lane+96]);
    __syncwarp();
    if(lane<20){
        float acc=pob[lane];
#pragma unroll 4
        for(int k=0;k<HID;k++) acc=fmaf(ctxS[warp][k],poW[k*20+lane],acc);
        out[(size_t)BATCH*SEQ*2 + rid*20 + lane]=acc;
    }else if(lane<22){
        int c=lane-20;
        float acc=subb[c];
#pragma unroll 4
        for(int k=0;k<HID;k++) acc=fmaf(rowS[warp][k],subW[k*2+c],acc);
        out[rid*2+c]=acc;
    }
}

extern "C" void kernel_launch(void* const* d_in, const int* in_sizes, int n_in,
                              void* d_out, int out_size){
    const int*   char_ids=(const int*)d_in[0];
    const int*   word_ids=(const int*)d_in[1];
    const int*   subj    =(const int*)d_in[2];
    const float* emb_char=(const float*)d_in[3];
    const float* emb_word=(const float*)d_in[4];
    const float* Wwc     =(const float*)d_in[5];
    const float* bwc     =(const float*)d_in[6];
    const float* l1_Wx   =(const float*)d_in[7];
    const float* l1_Wh   =(const float*)d_in[8];
    const float* l1_b    =(const float*)d_in[9];
    const float* l2_Wx   =(const float*)d_in[10];
    const float* l2_Wh   =(const float*)d_in[11];
    const float* l2_b    =(const float*)d_in[12];
    const float* beta_W  =(const float*)d_in[13];
    const float* beta_b  =(const float*)d_in[14];
    const float* gamma_W =(const float*)d_in[15];
    const float* gamma_b =(const float*)d_in[16];
    const float* sub_W   =(const float*)d_in[17];
    const float* sub_b   =(const float*)d_in[18];
    const float* po_W    =(const float*)d_in[19];
    const float* po_b    =(const float*)d_in[20];
    float* out=(float*)d_out;

    const int smem_bytes = SMEM_FLOATS * 4; // 228352
    cudaFuncSetAttribute(k_lstm, cudaFuncAttributeMaxDynamicSharedMemorySize, smem_bytes);

    k_trans<<<SEQ,BATCH>>>(char_ids,word_ids);
    k_table<<<1,512>>>(emb_char,emb_word,Wwc,bwc,l1_Wx,l1_b);
    k_lstm<<<128,256,smem_bytes>>>(l1_Wh,l2_Wx,l2_Wh,l2_b);
    k_subject<<<BATCH,256>>>(subj,beta_W,beta_b,gamma_W,gamma_b);
    k_post<<<(BATCH*SEQ)/8,256>>>(po_W,po_b,sub_W,sub_b,out);
}

// round 5
// speedup vs baseline: 1.4508x; 1.0299x over previous
#include <cuda_runtime.h>
#include <cooperative_groups.h>
namespace cg = cooperative_groups;

#define BATCH 256
#define SEQ 512
#define HID 128
#define GATES 512

// SMEM float offsets (k_lstm)
#define OFF_W1   0        // 16384 floats, layout (k>>2)*512 + j*4 + (k&3)
#define OFF_W2X  16384
#define OFF_W2H  32768
#define OFF_H1B  49152    // [2][8][128]
#define OFF_H2B  51200    // [2][8][128]
#define OFF_ZS   53248    // [2 parity][2 half][8][128] = 4096
#define OFF_B2S  57344    // [128]
#define OFF_CM   57472    // 512 bytes
#define SMEM_FLOATS 57600 // 230400 B

__device__ float g_P2[100*GATES];
__device__ __align__(8) unsigned char g_maskT[SEQ*BATCH];
__device__ __align__(8) unsigned char g_idxT[SEQ*BATCH];
__device__ float g_sent[(size_t)BATCH*SEQ*HID];
__device__ float g_beta[BATCH*HID];
__device__ float g_gamma[BATCH*HID];

__device__ __forceinline__ float sigm(float x){ return 0.5f*tanhf(0.5f*x)+0.5f; }

__global__ void k_trans(const int* __restrict__ ch, const int* __restrict__ wd){
    int t=blockIdx.x, b=threadIdx.x;
    int c=ch[b*SEQ+t], w=wd[b*SEQ+t];
    g_maskT[t*BATCH+b]=(unsigned char)(c==0);
    g_idxT [t*BATCH+b]=(unsigned char)(c*10+w);
}

__global__ void k_table(const float* __restrict__ emb_char,const float* __restrict__ emb_word,
                        const float* __restrict__ Wwc,const float* __restrict__ bwc,
                        const float* __restrict__ l1_Wx,const float* __restrict__ l1_b){
    __shared__ float xv[64];
    int tid=threadIdx.x; // 512
    for(int p=0;p<100;p++){
        int c=p/10, w=p%10;
        if(tid<64){
            float s=emb_char[c*64+tid]+bwc[tid];
            for(int d=0;d<32;d++) s=fmaf(emb_word[w*32+d],Wwc[d*64+tid],s);
            xv[tid]=s;
        }
        __syncthreads();
        float acc=l1_b[tid];
        for(int e=0;e<64;e++) acc=fmaf(xv[e],l1_Wx[e*GATES+tid],acc);
        g_P2[p*GATES+tid]=acc;
        __syncthreads();
    }
}

__global__ void __cluster_dims__(4,1,1) __launch_bounds__(256,1)
k_lstm(const float* __restrict__ Wh1g,const float* __restrict__ Wx2g,
       const float* __restrict__ Wh2g,const float* __restrict__ b2g){
    extern __shared__ float sm[];
    float* W1  = sm + OFF_W1;
    float* W2x = sm + OFF_W2X;
    float* W2h = sm + OFF_W2H;
    float* h1b = sm + OFF_H1B;
    float* h2b = sm + OFF_H2B;
    float* zs  = sm + OFF_ZS;
    float* b2s = sm + OFF_B2S;
    unsigned char* cmask = (unsigned char*)(sm + OFF_CM);

    const int tid = threadIdx.x, o = blockIdx.x & 3, cl = blockIdx.x >> 2;
    const int j = tid & 127, half = tid >> 7;
    const int gcol = (j >> 5) * 128 + o * 32 + (j & 31);
    const int rr = tid >> 5, ii = tid & 31;
    const int oc = o * 32 + ii;
    const int bb = cl * 8 + rr;

    // ---- prologue: weights into SMEM, k-major quad-interleaved ----
    for (int idx = tid; idx < 128 * 128; idx += 256) {
        int jj = idx & 127, k = idx >> 7;
        int gc = ((jj >> 5) << 7) + o * 32 + (jj & 31);
        int dst = (k >> 2) * 512 + jj * 4 + (k & 3);
        W1 [dst] = Wh1g[k * GATES + gc];
        W2x[dst] = Wx2g[k * GATES + gc];
        W2h[dst] = Wh2g[k * GATES + gc];
    }
    if (tid < 128) b2s[tid] = b2g[(tid >> 5) * 128 + o * 32 + (tid & 31)];
    for (int idx = tid; idx < 2048; idx += 256) { h1b[idx] = 0.f; h2b[idx] = 0.f; }
    for (int s = tid; s < SEQ; s += 256) {
        unsigned long long v = *(const unsigned long long*)(g_maskT + s * BATCH + cl * 8);
        unsigned mm = 0;
#pragma unroll
        for (int r = 0; r < 8; r++) mm |= ((unsigned)((v >> (8 * r)) & 1ull)) << r;
        cmask[s] = (unsigned char)mm;
    }
    __syncthreads();
    const float b2r = half ? b2s[j] : 0.f;

    cg::cluster_group cluster = cg::this_cluster();
    float* ph1[4]; float* ph2[4];
#pragma unroll
    for (int rk = 0; rk < 4; rk++) { ph1[rk] = cluster.map_shared_rank(h1b, rk); ph2[rk] = cluster.map_shared_rank(h2b, rk); }
    cluster.sync();

    const float* W1p = W1 + half * (16 * 512) + j * 4;   // half selects k in [64h, 64h+64)
    const float* Wtp = (half ? W2h : W2x) + j * 4;

    float c1 = 0.f, c2 = 0.f;
    int p = 0;

    for (int t = 0; t < SEQ; t++) {
        const int m = cmask[t];
        if (m == 0) {
            g_sent[((size_t)bb * SEQ + t) * HID + oc] = h2b[p * 1024 + rr * 128 + oc];
            continue;
        }
        const unsigned long long idx8 = *(const unsigned long long*)(g_idxT + t * BATCH + cl * 8);
        const int pq = p ^ 1;
        float* zsp = zs + p * 2048 + half * 1024;

        // ---- phase 1: L1 z (split-k halves), rows paired ----
        {
            unsigned mm = (unsigned)m;
            while (mm) {
                int ra = __ffs(mm) - 1; mm &= mm - 1;
                bool hasb = (mm != 0);
                int rb = hasb ? (__ffs(mm) - 1) : ra;
                if (hasb) mm &= mm - 1;
                const float* hA = h1b + p * 1024 + ra * 128 + half * 64;
                const float* hB = h1b + p * 1024 + rb * 128 + half * 64;
                float pa = 0.f, pb = 0.f;
                if (half == 0) {
                    pa = g_P2[(int)((idx8 >> (8 * ra)) & 255ull) * GATES + gcol];
                    pb = g_P2[(int)((idx8 >> (8 * rb)) & 255ull) * GATES + gcol];
                }
                float za = 0.f, zb = 0.f;
#pragma unroll
                for (int kq = 0; kq < 16; kq++) {
                    float4 w  = *(const float4*)(W1p + kq * 512);
                    float4 a4 = *(const float4*)(hA + kq * 4);
                    float4 b4 = *(const float4*)(hB + kq * 4);
                    za = fmaf(a4.x, w.x, za); za = fmaf(a4.y, w.y, za);
                    za = fmaf(a4.z, w.z, za); za = fmaf(a4.w, w.w, za);
                    zb = fmaf(b4.x, w.x, zb); zb = fmaf(b4.y, w.y, zb);
                    zb = fmaf(b4.z, w.z, zb); zb = fmaf(b4.w, w.w, zb);
                }
                zsp[ra * 128 + j] = za + pa;
                if (hasb) zsp[rb * 128 + j] = zb + pb;
            }
        }
        __syncthreads();

        // ---- phase 2: L1 gates + h1 exchange; inactive rows forward own cols ----
        const bool act = (m >> rr) & 1;
        const float* zp0 = zs + p * 2048 + rr * 128;
        float h1v;
        if (act) {
            float zi = zp0[ii]      + zp0[1024 + ii];
            float zf = zp0[32 + ii] + zp0[1024 + 32 + ii];
            float zg = zp0[64 + ii] + zp0[1024 + 64 + ii];
            float zo = zp0[96 + ii] + zp0[1024 + 96 + ii];
            float cn = sigm(zf) * c1 + sigm(zi) * tanhf(zg); c1 = cn;
            h1v = sigm(zo) * tanhf(cn);
        } else {
            h1v = h1b[p * 1024 + rr * 128 + oc];
            float h2k = h2b[p * 1024 + rr * 128 + oc];
#pragma unroll
            for (int rk = 0; rk < 4; rk++) ph2[rk][pq * 1024 + rr * 128 + oc] = h2k;
        }
#pragma unroll
        for (int rk = 0; rk < 4; rk++) ph1[rk][pq * 1024 + rr * 128 + oc] = h1v;

        cluster.sync();

        // ---- phase 3: L2 z (half 0: x-term w/ new h1, half 1: h-term w/ old h2) ----
        {
            const float* hbase = half ? (h2b + p * 1024) : (h1b + pq * 1024);
            unsigned mm = (unsigned)m;
            while (mm) {
                int ra = __ffs(mm) - 1; mm &= mm - 1;
                bool hasb = (mm != 0);
                int rb = hasb ? (__ffs(mm) - 1) : ra;
                if (hasb) mm &= mm - 1;
                const float* hA = hbase + ra * 128;
                const float* hB = hbase + rb * 128;
                float za = b2r, zb = b2r;
#pragma unroll
                for (int kq = 0; kq < 32; kq++) {
                    float4 w  = *(const float4*)(Wtp + kq * 512);
                    float4 a4 = *(const float4*)(hA + kq * 4);
                    float4 b4 = *(const float4*)(hB + kq * 4);
                    za = fmaf(a4.x, w.x, za); za = fmaf(a4.y, w.y, za);
                    za = fmaf(a4.z, w.z, za); za = fmaf(a4.w, w.w, za);
                    zb = fmaf(b4.x, w.x, zb); zb = fmaf(b4.y, w.y, zb);
                    zb = fmaf(b4.z, w.z, zb); zb = fmaf(b4.w, w.w, zb);
                }
                zsp[ra * 128 + j] = za;
                if (hasb) zsp[rb * 128 + j] = zb;
            }
        }
        __syncthreads();

        // ---- phase 4: L2 gates + h2 exchange + sent ----
        if (act) {
            float zi = zp0[ii]      + zp0[1024 + ii];
            float zf = zp0[32 + ii] + zp0[1024 + 32 + ii];
            float zg = zp0[64 + ii] + zp0[1024 + 64 + ii];
            float zo = zp0[96 + ii] + zp0[1024 + 96 + ii];
            float cn = sigm(zf) * c2 + sigm(zi) * tanhf(zg); c2 = cn;
            float h2v = sigm(zo) * tanhf(cn);
#pragma unroll
            for (int rk = 0; rk < 4; rk++) ph2[rk][pq * 1024 + rr * 128 + oc] = h2v;
            g_sent[((size_t)bb * SEQ + t) * HID + oc] = h2v;
        } else {
            g_sent[((size_t)bb * SEQ + t) * HID + oc] = h2b[p * 1024 + rr * 128 + oc];
        }
        // zs is parity double-buffered; no trailing barrier needed
        p = pq;
    }
    cluster.sync();        // no CTA exits while peers may still write its SMEM
}

__global__ void k_subject(const int* __restrict__ subj,
                          const float* __restrict__ betaW,const float* __restrict__ betab,
                          const float* __restrict__ gammaW,const float* __restrict__ gammab){
    __shared__ float sub[256];
    int b = blockIdx.x, tid = threadIdx.x;  // 256 threads
    int s0 = subj[b*2+0], s1 = subj[b*2+1];
    if (tid < 128) sub[tid] = g_sent[((size_t)b*SEQ+s0)*HID + tid];
    else           sub[tid] = g_sent[((size_t)b*SEQ+s1)*HID + (tid-128)];
    __syncthreads();
    int col = tid & 127;
    const float* Wm = (tid < 128) ? betaW : gammaW;
    float a = (tid < 128) ? betab[col] : gammab[col];
    for (int k = 0; k < 256; k++) a = fmaf(sub[k], Wm[k*HID + col], a);
    if (tid < 128) g_beta [b*HID + col] = a;
    else           g_gamma[b*HID + col] = a;
}

__global__ void __launch_bounds__(256) k_post(const float* __restrict__ poW,const float* __restrict__ pob,
                                              const float* __restrict__ subW,const float* __restrict__ subb,
                                              float* __restrict__ out){
    __shared__ float rowS[8][132];
    __shared__ float ctxS[8][132];
    int warp=threadIdx.x>>5, lane=threadIdx.x&31;
    size_t rid=(size_t)blockIdx.x*8+warp;      // b*512+t
    int b=(int)(rid>>9);
    const float* row=g_sent+rid*HID;
    float x0=row[lane], x1=row[lane+32], x2=row[lane+64], x3=row[lane+96];
    float s=x0+x1+x2+x3, q=x0*x0+x1*x1+x2*x2+x3*x3;
#pragma unroll
    for(int d=16;d;d>>=1){ s+=__shfl_xor_sync(0xffffffffu,s,d); q+=__shfl_xor_sync(0xffffffffu,q,d); }
    float u=s*(1.f/128.f);
    float v=fmaxf(q*(1.f/128.f)-u*u,0.f);
    float inv=rsqrtf(v+1e-12f);
    const float* gma=g_gamma+b*HID; const float* bta=g_beta+b*HID;
    rowS[warp][lane]   =x0; ctxS[warp][lane]   =fmaf(gma[lane]   *inv,(x0-u),bta[lane]);
    rowS[warp][lane+32]=x1; ctxS[warp][lane+32]=fmaf(gma[lane+32]*inv,(x1-u),bta[lane+32]);
    rowS[warp][lane+64]=x2; ctxS[warp][lane+64]=fmaf(gma[lane+64]*inv,(x2-u),bta[lane+64]);
    rowS[warp][lane+96]=x3; ctxS[warp][lane+96]=fmaf(gma[lane+96]*inv,(x3-u),bta[lane+96]);
    __syncwarp();
    if(lane<20){
        float acc=pob[lane];
#pragma unroll 4
        for(int k=0;k<HID;k++) acc=fmaf(ctxS[warp][k],poW[k*20+lane],acc);
        out[(size_t)BATCH*SEQ*2 + rid*20 + lane]=acc;
    }else if(lane<22){
        int c=lane-20;
        float acc=subb[c];
#pragma unroll 4
        for(int k=0;k<HID;k++) acc=fmaf(rowS[warp][k],subW[k*2+c],acc);
        out[rid*2+c]=acc;
    }
}

extern "C" void kernel_launch(void* const* d_in, const int* in_sizes, int n_in,
                              void* d_out, int out_size){
    const int*   char_ids=(const int*)d_in[0];
    const int*   word_ids=(const int*)d_in[1];
    const int*   subj    =(const int*)d_in[2];
    const float* emb_char=(const float*)d_in[3];
    const float* emb_word=(const float*)d_in[4];
    const float* Wwc     =(const float*)d_in[5];
    const float* bwc     =(const float*)d_in[6];
    const float* l1_Wx   =(const float*)d_in[7];
    const float* l1_Wh   =(const float*)d_in[8];
    const float* l1_b    =(const float*)d_in[9];
    const float* l2_Wx   =(const float*)d_in[10];
    const float* l2_Wh   =(const float*)d_in[11];
    const float* l2_b    =(const float*)d_in[12];
    const float* beta_W  =(const float*)d_in[13];
    const float* beta_b  =(const float*)d_in[14];
    const float* gamma_W =(const float*)d_in[15];
    const float* gamma_b =(const float*)d_in[16];
    const float* sub_W   =(const float*)d_in[17];
    const float* sub_b   =(const float*)d_in[18];
    const float* po_W    =(const float*)d_in[19];
    const float* po_b    =(const float*)d_in[20];
    float* out=(float*)d_out;

    const int smem_bytes = SMEM_FLOATS * 4; // 230400
    cudaFuncSetAttribute(k_lstm, cudaFuncAttributeMaxDynamicSharedMemorySize, smem_bytes);

    k_trans<<<SEQ,BATCH>>>(char_ids,word_ids);
    k_table<<<1,512>>>(emb_char,emb_word,Wwc,bwc,l1_Wx,l1_b);
    k_lstm<<<128,256,smem_bytes>>>(l1_Wh,l2_Wx,l2_Wh,l2_b);
    k_subject<<<BATCH,256>>>(subj,beta_W,beta_b,gamma_W,gamma_b);
    k_post<<<(BATCH*SEQ)/8,256>>>(po_W,po_b,sub_W,sub_b,out);
}

// round 6
// speedup vs baseline: 1.8403x; 1.2684x over previous
#include <cuda_runtime.h>
#include <cooperative_groups.h>
namespace cg = cooperative_groups;

#define BATCH 256
#define SEQ 512
#define HID 128
#define GATES 512

// SMEM float offsets (k_lstm)
#define OFF_W1   0        // 16384 floats, layout (k>>2)*512 + j*4 + (k&3)  (prologue staging)
#define OFF_W2X  16384
#define OFF_W2H  32768
#define OFF_H1B  49152    // [2][8][128]
#define OFF_H2B  51200    // [2][8][128]
#define OFF_ZS   53248    // [2 parity][2 half][8][128] = 4096
#define OFF_B2S  57344    // [128]
#define OFF_CM   57472    // 512 bytes
#define SMEM_FLOATS 57600 // 230400 B

__device__ float g_P2[100*GATES];
__device__ __align__(8) unsigned char g_maskT[SEQ*BATCH];
__device__ __align__(8) unsigned char g_idxT[SEQ*BATCH];
__device__ float g_sent[(size_t)BATCH*SEQ*HID];
__device__ float g_beta[BATCH*HID];
__device__ float g_gamma[BATCH*HID];

__device__ __forceinline__ float sigm(float x){ return 0.5f*tanhf(0.5f*x)+0.5f; }

__global__ void k_trans(const int* __restrict__ ch, const int* __restrict__ wd){
    int t=blockIdx.x, b=threadIdx.x;
    int c=ch[b*SEQ+t], w=wd[b*SEQ+t];
    g_maskT[t*BATCH+b]=(unsigned char)(c==0);
    g_idxT [t*BATCH+b]=(unsigned char)(c*10+w);
}

__global__ void k_table(const float* __restrict__ emb_char,const float* __restrict__ emb_word,
                        const float* __restrict__ Wwc,const float* __restrict__ bwc,
                        const float* __restrict__ l1_Wx,const float* __restrict__ l1_b){
    __shared__ float xv[64];
    int tid=threadIdx.x; // 512
    for(int p=0;p<100;p++){
        int c=p/10, w=p%10;
        if(tid<64){
            float s=emb_char[c*64+tid]+bwc[tid];
            for(int d=0;d<32;d++) s=fmaf(emb_word[w*32+d],Wwc[d*64+tid],s);
            xv[tid]=s;
        }
        __syncthreads();
        float acc=l1_b[tid];
        for(int e=0;e<64;e++) acc=fmaf(xv[e],l1_Wx[e*GATES+tid],acc);
        g_P2[p*GATES+tid]=acc;
        __syncthreads();
    }
}

__global__ void __cluster_dims__(4,1,1) __launch_bounds__(256,1)
k_lstm(const float* __restrict__ Wh1g,const float* __restrict__ Wx2g,
       const float* __restrict__ Wh2g,const float* __restrict__ b2g){
    extern __shared__ float sm[];
    float* W1  = sm + OFF_W1;
    float* W2x = sm + OFF_W2X;
    float* W2h = sm + OFF_W2H;
    float* h1b = sm + OFF_H1B;
    float* h2b = sm + OFF_H2B;
    float* zs  = sm + OFF_ZS;
    float* b2s = sm + OFF_B2S;
    unsigned char* cmask = (unsigned char*)(sm + OFF_CM);

    const int tid = threadIdx.x, o = blockIdx.x & 3, cl = blockIdx.x >> 2;
    const int j = tid & 127, half = tid >> 7;
    const int gcol = (j >> 5) * 128 + o * 32 + (j & 31);
    const int rr = tid >> 5, ii = tid & 31;
    const int oc = o * 32 + ii;
    const int bb = cl * 8 + rr;

    // ---- prologue: weights into SMEM staging (coalesced), then into registers ----
    for (int idx = tid; idx < 128 * 128; idx += 256) {
        int jj = idx & 127, k = idx >> 7;
        int gc = ((jj >> 5) << 7) + o * 32 + (jj & 31);
        int dst = (k >> 2) * 512 + jj * 4 + (k & 3);
        W1 [dst] = Wh1g[k * GATES + gc];
        W2x[dst] = Wx2g[k * GATES + gc];
        W2h[dst] = Wh2g[k * GATES + gc];
    }
    if (tid < 128) b2s[tid] = b2g[(tid >> 5) * 128 + o * 32 + (tid & 31)];
    for (int idx = tid; idx < 2048; idx += 256) { h1b[idx] = 0.f; h2b[idx] = 0.f; }
    for (int s = tid; s < SEQ; s += 256) {
        unsigned long long v = *(const unsigned long long*)(g_maskT + s * BATCH + cl * 8);
        unsigned mm = 0;
#pragma unroll
        for (int r = 0; r < 8; r++) mm |= ((unsigned)((v >> (8 * r)) & 1ull)) << r;
        cmask[s] = (unsigned char)mm;
    }
    __syncthreads();
    const float b2r = half ? b2s[j] : 0.f;

    // register-resident weights: 48 float4 = 192 regs
    float4 w1r[16];
    float4 wtr[32];
    {
        const float* W1p = W1 + half * (16 * 512) + j * 4;
        const float* Wtp = (half ? W2h : W2x) + j * 4;
#pragma unroll
        for (int kq = 0; kq < 16; kq++) w1r[kq] = *(const float4*)(W1p + kq * 512);
#pragma unroll
        for (int kq = 0; kq < 32; kq++) wtr[kq] = *(const float4*)(Wtp + kq * 512);
    }

    cg::cluster_group cluster = cg::this_cluster();
    cluster.sync();

    float c1 = 0.f, c2 = 0.f;
    int p = 0;

    for (int t = 0; t < SEQ; t++) {
        const int m = cmask[t];
        if (m == 0) {
            g_sent[((size_t)bb * SEQ + t) * HID + oc] = h2b[p * 1024 + rr * 128 + oc];
            continue;
        }
        const unsigned long long idx8 = *(const unsigned long long*)(g_idxT + t * BATCH + cl * 8);
        const int pq = p ^ 1;
        float* zsp = zs + p * 2048 + half * 1024;

        // ---- phase 1: L1 z (split-k halves), rows paired, weights in regs ----
        {
            unsigned mm = (unsigned)m;
            while (mm) {
                int ra = __ffs(mm) - 1; mm &= mm - 1;
                bool hasb = (mm != 0);
                int rb = hasb ? (__ffs(mm) - 1) : ra;
                if (hasb) mm &= mm - 1;
                const float* hA = h1b + p * 1024 + ra * 128 + half * 64;
                const float* hB = h1b + p * 1024 + rb * 128 + half * 64;
                float pa = 0.f, pb = 0.f;
                if (half == 0) {
                    pa = g_P2[(int)((idx8 >> (8 * ra)) & 255ull) * GATES + gcol];
                    pb = g_P2[(int)((idx8 >> (8 * rb)) & 255ull) * GATES + gcol];
                }
                float za = 0.f, zb = 0.f;
#pragma unroll
                for (int kq = 0; kq < 16; kq++) {
                    float4 a4 = *(const float4*)(hA + kq * 4);   // broadcast LDS
                    float4 b4 = *(const float4*)(hB + kq * 4);
                    za = fmaf(a4.x, w1r[kq].x, za); za = fmaf(a4.y, w1r[kq].y, za);
                    za = fmaf(a4.z, w1r[kq].z, za); za = fmaf(a4.w, w1r[kq].w, za);
                    zb = fmaf(b4.x, w1r[kq].x, zb); zb = fmaf(b4.y, w1r[kq].y, zb);
                    zb = fmaf(b4.z, w1r[kq].z, zb); zb = fmaf(b4.w, w1r[kq].w, zb);
                }
                zsp[ra * 128 + j] = za + pa;
                if (hasb) zsp[rb * 128 + j] = zb + pb;
            }
        }
        __syncthreads();

        // ---- phase 2: L1 gates + h1 exchange; inactive rows forward own cols ----
        const bool act = (m >> rr) & 1;
        const float* zp0 = zs + p * 2048 + rr * 128;
        float h1v;
        if (act) {
            float zi = zp0[ii]      + zp0[1024 + ii];
            float zf = zp0[32 + ii] + zp0[1024 + 32 + ii];
            float zg = zp0[64 + ii] + zp0[1024 + 64 + ii];
            float zo = zp0[96 + ii] + zp0[1024 + 96 + ii];
            float cn = sigm(zf) * c1 + sigm(zi) * tanhf(zg); c1 = cn;
            h1v = sigm(zo) * tanhf(cn);
        } else {
            h1v = h1b[p * 1024 + rr * 128 + oc];
            float h2k = h2b[p * 1024 + rr * 128 + oc];
#pragma unroll
            for (int rk = 0; rk < 4; rk++)
                cluster.map_shared_rank(h2b, rk)[pq * 1024 + rr * 128 + oc] = h2k;
        }
#pragma unroll
        for (int rk = 0; rk < 4; rk++)
            cluster.map_shared_rank(h1b, rk)[pq * 1024 + rr * 128 + oc] = h1v;

        cluster.sync();

        // ---- phase 3: L2 z (half 0: x-term w/ new h1, half 1: h-term w/ old h2) ----
        {
            const float* hbase = half ? (h2b + p * 1024) : (h1b + pq * 1024);
            unsigned mm = (unsigned)m;
            while (mm) {
                int ra = __ffs(mm) - 1; mm &= mm - 1;
                bool hasb = (mm != 0);
                int rb = hasb ? (__ffs(mm) - 1) : ra;
                if (hasb) mm &= mm - 1;
                const float* hA = hbase + ra * 128;
                const float* hB = hbase + rb * 128;
                float za = b2r, zb = b2r;
#pragma unroll
                for (int kq = 0; kq < 32; kq++) {
                    float4 a4 = *(const float4*)(hA + kq * 4);
                    float4 b4 = *(const float4*)(hB + kq * 4);
                    za = fmaf(a4.x, wtr[kq].x, za); za = fmaf(a4.y, wtr[kq].y, za);
                    za = fmaf(a4.z, wtr[kq].z, za); za = fmaf(a4.w, wtr[kq].w, za);
                    zb = fmaf(b4.x, wtr[kq].x, zb); zb = fmaf(b4.y, wtr[kq].y, zb);
                    zb = fmaf(b4.z, wtr[kq].z, zb); zb = fmaf(b4.w, wtr[kq].w, zb);
                }
                zsp[ra * 128 + j] = za;
                if (hasb) zsp[rb * 128 + j] = zb;
            }
        }
        __syncthreads();

        // ---- phase 4: L2 gates + h2 exchange + sent ----
        if (act) {
            float zi = zp0[ii]      + zp0[1024 + ii];
            float zf = zp0[32 + ii] + zp0[1024 + 32 + ii];
            float zg = zp0[64 + ii] + zp0[1024 + 64 + ii];
            float zo = zp0[96 + ii] + zp0[1024 + 96 + ii];
            float cn = sigm(zf) * c2 + sigm(zi) * tanhf(zg); c2 = cn;
            float h2v = sigm(zo) * tanhf(cn);
#pragma unroll
            for (int rk = 0; rk < 4; rk++)
                cluster.map_shared_rank(h2b, rk)[pq * 1024 + rr * 128 + oc] = h2v;
            g_sent[((size_t)bb * SEQ + t) * HID + oc] = h2v;
        } else {
            g_sent[((size_t)bb * SEQ + t) * HID + oc] = h2b[p * 1024 + rr * 128 + oc];
        }
        // zs is parity double-buffered; no trailing barrier needed
        p = pq;
    }
    cluster.sync();        // no CTA exits while peers may still write its SMEM
}

__global__ void k_subject(const int* __restrict__ subj,
                          const float* __restrict__ betaW,const float* __restrict__ betab,
                          const float* __restrict__ gammaW,const float* __restrict__ gammab){
    __shared__ float sub[256];
    int b = blockIdx.x, tid = threadIdx.x;  // 256 threads
    int s0 = subj[b*2+0], s1 = subj[b*2+1];
    if (tid < 128) sub[tid] = g_sent[((size_t)b*SEQ+s0)*HID + tid];
    else           sub[tid] = g_sent[((size_t)b*SEQ+s1)*HID + (tid-128)];
    __syncthreads();
    int col = tid & 127;
    const float* Wm = (tid < 128) ? betaW : gammaW;
    float a = (tid < 128) ? betab[col] : gammab[col];
    for (int k = 0; k < 256; k++) a = fmaf(sub[k], Wm[k*HID + col], a);
    if (tid < 128) g_beta [b*HID + col] = a;
    else           g_gamma[b*HID + col] = a;
}

__global__ void __launch_bounds__(256) k_post(const float* __restrict__ poW,const float* __restrict__ pob,
                                              const float* __restrict__ subW,const float* __restrict__ subb,
                                              float* __restrict__ out){
    __shared__ float rowS[8][132];
    __shared__ float ctxS[8][132];
    int warp=threadIdx.x>>5, lane=threadIdx.x&31;
    size_t rid=(size_t)blockIdx.x*8+warp;      // b*512+t
    int b=(int)(rid>>9);
    const float* row=g_sent+rid*HID;
    float x0=row[lane], x1=row[lane+32], x2=row[lane+64], x3=row[lane+96];
    float s=x0+x1+x2+x3, q=x0*x0+x1*x1+x2*x2+x3*x3;
#pragma unroll
    for(int d=16;d;d>>=1){ s+=__shfl_xor_sync(0xffffffffu,s,d); q+=__shfl_xor_sync(0xffffffffu,q,d); }
    float u=s*(1.f/128.f);
    float v=fmaxf(q*(1.f/128.f)-u*u,0.f);
    float inv=rsqrtf(v+1e-12f);
    const float* gma=g_gamma+b*HID; const float* bta=g_beta+b*HID;
    rowS[warp][lane]   =x0; ctxS[warp][lane]   =fmaf(gma[lane]   *inv,(x0-u),bta[lane]);
    rowS[warp][lane+32]=x1; ctxS[warp][lane+32]=fmaf(gma[lane+32]*inv,(x1-u),bta[lane+32]);
    rowS[warp][lane+64]=x2; ctxS[warp][lane+64]=fmaf(gma[lane+64]*inv,(x2-u),bta[lane+64]);
    rowS[warp][lane+96]=x3; ctxS[warp][lane+96]=fmaf(gma[lane+96]*inv,(x3-u),bta[lane+96]);
    __syncwarp();
    if(lane<20){
        float acc=pob[lane];
#pragma unroll 4
        for(int k=0;k<HID;k++) acc=fmaf(ctxS[warp][k],poW[k*20+lane],acc);
        out[(size_t)BATCH*SEQ*2 + rid*20 + lane]=acc;
    }else if(lane<22){
        int c=lane-20;
        float acc=subb[c];
#pragma unroll 4
        for(int k=0;k<HID;k++) acc=fmaf(rowS[warp][k],subW[k*2+c],acc);
        out[rid*2+c]=acc;
    }
}

extern "C" void kernel_launch(void* const* d_in, const int* in_sizes, int n_in,
                              void* d_out, int out_size){
    const int*   char_ids=(const int*)d_in[0];
    const int*   word_ids=(const int*)d_in[1];
    const int*   subj    =(const int*)d_in[2];
    const float* emb_char=(const float*)d_in[3];
    const float* emb_word=(const float*)d_in[4];
    const float* Wwc     =(const float*)d_in[5];
    const float* bwc     =(const float*)d_in[6];
    const float* l1_Wx   =(const float*)d_in[7];
    const float* l1_Wh   =(const float*)d_in[8];
    const float* l1_b    =(const float*)d_in[9];
    const float* l2_Wx   =(const float*)d_in[10];
    const float* l2_Wh   =(const float*)d_in[11];
    const float* l2_b    =(const float*)d_in[12];
    const float* beta_W  =(const float*)d_in[13];
    const float* beta_b  =(const float*)d_in[14];
    const float* gamma_W =(const float*)d_in[15];
    const float* gamma_b =(const float*)d_in[16];
    const float* sub_W   =(const float*)d_in[17];
    const float* sub_b   =(const float*)d_in[18];
    const float* po_W    =(const float*)d_in[19];
    const float* po_b    =(const float*)d_in[20];
    float* out=(float*)d_out;

    const int smem_bytes = SMEM_FLOATS * 4; // 230400
    cudaFuncSetAttribute(k_lstm, cudaFuncAttributeMaxDynamicSharedMemorySize, smem_bytes);

    k_trans<<<SEQ,BATCH>>>(char_ids,word_ids);
    k_table<<<1,512>>>(emb_char,emb_word,Wwc,bwc,l1_Wx,l1_b);
    k_lstm<<<128,256,smem_bytes>>>(l1_Wh,l2_Wx,l2_Wh,l2_b);
    k_subject<<<BATCH,256>>>(subj,beta_W,beta_b,gamma_W,gamma_b);
    k_post<<<(BATCH*SEQ)/8,256>>>(po_W,po_b,sub_W,sub_b,out);
}